// round 12
// baseline (speedup 1.0000x reference)
#include <cuda_runtime.h>
#include <cuda_bf16.h>
#include <mma.h>
#include <math.h>
#include <stdint.h>
#include <type_traits>

using namespace nvcuda;

#define Bb_ 4
#define S_ 1024
#define HID_ 4096
#define NH_ 32
#define HD_ 128
#define O3_ 12288
#define R_ 32
#define SCALE_ 0.08838834764831845f

typedef __nv_bfloat16 bf16;

// RULE (hard-won): device globals are referenced ONLY inside kernel bodies,
// never passed as kernel arguments from host code.

// ---- fp32 stage buffers ----
__device__ float g_qkv[(size_t)Bb_ * S_ * O3_];        // 201 MB
__device__ float g_scores[(size_t)Bb_ * NH_ * S_ * S_];// 512 MB (fp32 scores -> grouped probs)
__device__ float g_attn[(size_t)Bb_ * S_ * HID_];      // 67 MB
// ---- planar hi/lo presplit buffers ----
__device__ bf16 g_hsH[(size_t)Bb_ * S_ * HID_];
__device__ bf16 g_hsL[(size_t)Bb_ * S_ * HID_];
__device__ bf16 g_wqH[(size_t)O3_ * HID_];
__device__ bf16 g_wqL[(size_t)O3_ * HID_];
__device__ bf16 g_wdH[(size_t)HID_ * HID_];
__device__ bf16 g_wdL[(size_t)HID_ * HID_];
__device__ bf16 g_qH[(size_t)Bb_ * NH_ * S_ * HD_];
__device__ bf16 g_qL[(size_t)Bb_ * NH_ * S_ * HD_];
__device__ bf16 g_kH[(size_t)Bb_ * NH_ * S_ * HD_];
__device__ bf16 g_kL[(size_t)Bb_ * NH_ * S_ * HD_];
__device__ bf16 g_attnH[(size_t)Bb_ * S_ * HID_];
__device__ bf16 g_attnL[(size_t)Bb_ * S_ * HID_];
__device__ bf16 g_midH[Bb_ * S_ * R_];
__device__ bf16 g_midL[Bb_ * S_ * R_];
__device__ bf16 g_lorH[(size_t)Bb_ * O3_ * R_];
__device__ bf16 g_lorL[(size_t)Bb_ * O3_ * R_];

__device__ __forceinline__ void split1(float x, bf16& h, bf16& l) {
    h = __float2bfloat16(x);
    l = __float2bfloat16(x - __bfloat162float(h));
}

__device__ __forceinline__ void split4planar(float4 v, bf16* H, bf16* L) {
    bf16 h0, h1, h2, h3, l0, l1, l2, l3;
    split1(v.x, h0, l0); split1(v.y, h1, l1);
    split1(v.z, h2, l2); split1(v.w, h3, l3);
    __nv_bfloat162 a, b, c, d;
    a.x = h0; a.y = h1; b.x = h2; b.y = h3;
    c.x = l0; c.y = l1; d.x = l2; d.y = l3;
    *reinterpret_cast<__nv_bfloat162*>(H)     = a;
    *reinterpret_cast<__nv_bfloat162*>(H + 2) = b;
    *reinterpret_cast<__nv_bfloat162*>(L)     = c;
    *reinterpret_cast<__nv_bfloat162*>(L + 2) = d;
}

// grouped layout (PV probs only): elem e -> hi at 8(e/4)+e%4, lo at +4
__device__ __forceinline__ uint4 split4pack(float4 v) {
    bf16 h0, h1, h2, h3, l0, l1, l2, l3;
    split1(v.x, h0, l0); split1(v.y, h1, l1);
    split1(v.z, h2, l2); split1(v.w, h3, l3);
    __nv_bfloat162 a, b, c, d;
    a.x = h0; a.y = h1; b.x = h2; b.y = h3;
    c.x = l0; c.y = l1; d.x = l2; d.y = l3;
    uint4 r;
    r.x = *reinterpret_cast<uint32_t*>(&a);
    r.y = *reinterpret_cast<uint32_t*>(&b);
    r.z = *reinterpret_cast<uint32_t*>(&c);
    r.w = *reinterpret_cast<uint32_t*>(&d);
    return r;
}

__device__ __forceinline__ void cp_async16(void* d, const void* g) {
    uint32_t a = (uint32_t)__cvta_generic_to_shared(d);
    asm volatile("cp.async.cg.shared.global [%0],[%1],16;\n" ::"r"(a), "l"(g));
}
#define CP_COMMIT asm volatile("cp.async.commit_group;\n" ::)
#define CP_WAIT2  asm volatile("cp.async.wait_group 2;\n" ::)

// ============ cp.async 4-stage planar-presplit NT GEMM ============
// C[m,n] = (AH+AL)[m,:] . (BH+BL)[n,:]^T (3-term), fp32 accum.
// Block 128x128, 8 warps (2x4), warp 64x32, BK=16, dynamic smem 96KB.
template <int LORA, int SCALEOUT>
__device__ __forceinline__ void gemm_pipe(
    const bf16* __restrict__ AH, const bf16* __restrict__ AL, const int lda,
    const bf16* __restrict__ BH, const bf16* __restrict__ BL, const int ldb,
    float* __restrict__ C, const int ldc,
    const int klim, const int bm, const int bn,
    const bf16* __restrict__ midH, const bf16* __restrict__ midL,
    const bf16* __restrict__ lorH, const bf16* __restrict__ lorL)
{
    extern __shared__ __align__(16) bf16 sm[];        // [4 stages][4 planes][128][24]
    const int t = threadIdx.x;
    const int warp = t >> 5;
    const int wm = warp >> 2, wn = warp & 3;
    const int row = t >> 1, half = t & 1;             // copy assignment

    const int kT = klim >> 4;
    const int total = kT + (LORA ? 2 : 0);

    auto smP = [&](int st, int pl) -> bf16* { return sm + (size_t)(st * 4 + pl) * (128 * 24); };

    auto issue = [&](int s) {
        const int st = s & 3;
        const bool tail = LORA && (s >= kT);
        const int k0 = tail ? ((s - kT) << 4) : (s << 4);
        const bf16* s0;
        const bf16* s1;
        const bf16* s2;
        const bf16* s3;
        if (!tail) {
            s0 = AH + (size_t)(bm * 128 + row) * lda + k0 + half * 8;
            s1 = AL + (size_t)(bm * 128 + row) * lda + k0 + half * 8;
            s2 = BH + (size_t)(bn * 128 + row) * ldb + k0 + half * 8;
            s3 = BL + (size_t)(bn * 128 + row) * ldb + k0 + half * 8;
        } else {
            s0 = midH + (size_t)(bm * 128 + row) * R_ + k0 + half * 8;
            s1 = midL + (size_t)(bm * 128 + row) * R_ + k0 + half * 8;
            s2 = lorH + (size_t)(bn * 128 + row) * R_ + k0 + half * 8;
            s3 = lorL + (size_t)(bn * 128 + row) * R_ + k0 + half * 8;
        }
        bf16* dbase = sm + (size_t)st * 4 * (128 * 24) + row * 24 + half * 8;
        cp_async16(dbase + 0 * (128 * 24), s0);
        cp_async16(dbase + 1 * (128 * 24), s1);
        cp_async16(dbase + 2 * (128 * 24), s2);
        cp_async16(dbase + 3 * (128 * 24), s3);
    };

    wmma::fragment<wmma::accumulator, 16, 16, 16, float> cfr[4][2];
#pragma unroll
    for (int mi = 0; mi < 4; mi++)
#pragma unroll
        for (int ni = 0; ni < 2; ni++) wmma::fill_fragment(cfr[mi][ni], 0.0f);

    issue(0); CP_COMMIT;
    issue(1); CP_COMMIT;
    issue(2); CP_COMMIT;

    for (int tt = 0; tt < total; tt++) {
        CP_WAIT2;                     // stage tt arrived (FIFO group retire)
        __syncthreads();              // all threads' data visible; prev readers done
        if (tt + 3 < total) issue(tt + 3);
        CP_COMMIT;                    // unconditional: keeps group count aligned
        const int st = tt & 3;
        const bf16* pAH = smP(st, 0);
        const bf16* pAL = smP(st, 1);
        const bf16* pBH = smP(st, 2);
        const bf16* pBL = smP(st, 3);

        wmma::fragment<wmma::matrix_b, 16, 16, 16, bf16, wmma::col_major> bH[2], bL[2];
#pragma unroll
        for (int ni = 0; ni < 2; ni++) {
            wmma::load_matrix_sync(bH[ni], pBH + (wn * 32 + ni * 16) * 24, 24);
            wmma::load_matrix_sync(bL[ni], pBL + (wn * 32 + ni * 16) * 24, 24);
        }
#pragma unroll
        for (int mi = 0; mi < 4; mi++) {
            wmma::fragment<wmma::matrix_a, 16, 16, 16, bf16, wmma::row_major> aH, aL;
            wmma::load_matrix_sync(aH, pAH + (wm * 64 + mi * 16) * 24, 24);
            wmma::load_matrix_sync(aL, pAL + (wm * 64 + mi * 16) * 24, 24);
#pragma unroll
            for (int ni = 0; ni < 2; ni++) {
                wmma::mma_sync(cfr[mi][ni], aH, bH[ni], cfr[mi][ni]);
                wmma::mma_sync(cfr[mi][ni], aH, bL[ni], cfr[mi][ni]);
                wmma::mma_sync(cfr[mi][ni], aL, bH[ni], cfr[mi][ni]);
            }
        }
    }

#pragma unroll
    for (int mi = 0; mi < 4; mi++)
#pragma unroll
        for (int ni = 0; ni < 2; ni++) {
            if (SCALEOUT) {
#pragma unroll
                for (int e = 0; e < cfr[mi][ni].num_elements; e++) cfr[mi][ni].x[e] *= SCALE_;
            }
            wmma::store_matrix_sync(
                C + (size_t)(bm * 128 + wm * 64 + mi * 16) * ldc + bn * 128 + wn * 32 + ni * 16,
                cfr[mi][ni], ldc, wmma::mem_row_major);
        }
}

// ============ R11-proven register-staged core (PV only) ============
// A grouped-presplit bf16 (probs), B K-major fp32 (V in g_qkv), in-loop split.
__device__ __forceinline__ void gemm_pv_core(
    const bf16* __restrict__ Agrp, const int lda,
    const float* __restrict__ Bv, const int ldb,
    float* __restrict__ C, const int ldc,
    const int klim, const int bm)
{
    __shared__ __align__(16) bf16 smA[2][2][128][24];
    constexpr int BSTG = 16 * 136;
    __shared__ __align__(16) bf16 smB[2][2 * BSTG];

    const int t = threadIdx.x;
    const int warp = t >> 5;
    const int wm = warp >> 2, wn = warp & 3;

    wmma::fragment<wmma::accumulator, 16, 16, 16, float> cfr[4][2];
#pragma unroll
    for (int mi = 0; mi < 4; mi++)
#pragma unroll
        for (int ni = 0; ni < 2; ni++) wmma::fill_fragment(cfr[mi][ni], 0.0f);

    const int kT = klim >> 4;
    float4 fB[2];
    uint4  uA[2];

    auto loadT = [&](int tt) {
        const int k0 = tt << 4;
#pragma unroll
        for (int i = 0; i < 2; i++) {
            int idx = i * 256 + t;
            int row = idx >> 2, q4 = (idx & 3) * 4;
            const bf16* src = Agrp + (size_t)(bm * 128 + row) * (2 * lda) + 2 * (k0 + q4);
            uA[i] = *reinterpret_cast<const uint4*>(src);
            int kr = idx >> 5, nc = (idx & 31) * 4;
            fB[i] = *reinterpret_cast<const float4*>(
                Bv + (size_t)(k0 + kr) * ldb + nc);
        }
    };

    auto storeT = [&](int st) {
#pragma unroll
        for (int i = 0; i < 2; i++) {
            int idx = i * 256 + t;
            int row = idx >> 2, q4 = (idx & 3) * 4;
            *reinterpret_cast<uint2*>(&smA[st][0][row][q4]) = make_uint2(uA[i].x, uA[i].y);
            *reinterpret_cast<uint2*>(&smA[st][1][row][q4]) = make_uint2(uA[i].z, uA[i].w);
            int kr = idx >> 5, nc = (idx & 31) * 4;
            bf16 h0, h1, h2, h3, l0, l1, l2, l3;
            split1(fB[i].x, h0, l0); split1(fB[i].y, h1, l1);
            split1(fB[i].z, h2, l2); split1(fB[i].w, h3, l3);
            __nv_bfloat162 a, b, c, d;
            a.x = h0; a.y = h1; b.x = h2; b.y = h3;
            c.x = l0; c.y = l1; d.x = l2; d.y = l3;
            *reinterpret_cast<__nv_bfloat162*>(&smB[st][kr * 136 + nc])         = a;
            *reinterpret_cast<__nv_bfloat162*>(&smB[st][kr * 136 + nc + 2])     = b;
            *reinterpret_cast<__nv_bfloat162*>(&smB[st][BSTG + kr * 136 + nc])     = c;
            *reinterpret_cast<__nv_bfloat162*>(&smB[st][BSTG + kr * 136 + nc + 2]) = d;
        }
    };

    loadT(0);
    storeT(0);
    __syncthreads();

    for (int tt = 0; tt < kT; tt++) {
        if (tt + 1 < kT) loadT(tt + 1);
        const int st = tt & 1;

        wmma::fragment<wmma::matrix_b, 16, 16, 16, bf16, wmma::row_major> bH[2], bL[2];
#pragma unroll
        for (int ni = 0; ni < 2; ni++) {
            wmma::load_matrix_sync(bH[ni], &smB[st][wn * 32 + ni * 16], 136);
            wmma::load_matrix_sync(bL[ni], &smB[st][BSTG + wn * 32 + ni * 16], 136);
        }
#pragma unroll
        for (int mi = 0; mi < 4; mi++) {
            wmma::fragment<wmma::matrix_a, 16, 16, 16, bf16, wmma::row_major> aH, aL;
            wmma::load_matrix_sync(aH, &smA[st][0][wm * 64 + mi * 16][0], 24);
            wmma::load_matrix_sync(aL, &smA[st][1][wm * 64 + mi * 16][0], 24);
#pragma unroll
            for (int ni = 0; ni < 2; ni++) {
                wmma::mma_sync(cfr[mi][ni], aH, bH[ni], cfr[mi][ni]);
                wmma::mma_sync(cfr[mi][ni], aH, bL[ni], cfr[mi][ni]);
                wmma::mma_sync(cfr[mi][ni], aL, bH[ni], cfr[mi][ni]);
            }
        }
        if (tt + 1 < kT) storeT((tt + 1) & 1);
        __syncthreads();
    }

#pragma unroll
    for (int mi = 0; mi < 4; mi++)
#pragma unroll
        for (int ni = 0; ni < 2; ni++)
            wmma::store_matrix_sync(
                C + (size_t)(bm * 128 + wm * 64 + mi * 16) * ldc + wn * 32 + ni * 16,
                cfr[mi][ni], ldc, wmma::mem_row_major);
}

// ---------------- GEMM wrapper kernels ----------------
__global__ __launch_bounds__(256, 2) void k_qkv()
{
    const int b = (int)(blockIdx.y >> 3);
    gemm_pipe<1, 0>(g_hsH, g_hsL, HID_, g_wqH, g_wqL, HID_, g_qkv, O3_,
                    HID_, blockIdx.y, blockIdx.x,
                    g_midH, g_midL,
                    g_lorH + (size_t)b * O3_ * R_, g_lorL + (size_t)b * O3_ * R_);
}

__global__ __launch_bounds__(256, 2) void k_scores()
{
    if (blockIdx.x > blockIdx.y) return;
    const size_t z = blockIdx.z;
    gemm_pipe<0, 1>(g_qH + z * S_ * HD_, g_qL + z * S_ * HD_, HD_,
                    g_kH + z * S_ * HD_, g_kL + z * S_ * HD_, HD_,
                    g_scores + z * S_ * S_, S_,
                    HD_, blockIdx.y, blockIdx.x,
                    nullptr, nullptr, nullptr, nullptr);
}

__global__ __launch_bounds__(256, 2) void k_pv()
{
    const size_t z = blockIdx.y;
    const int b = (int)(z >> 5), h = (int)(z & 31);
    const int bm = (int)blockIdx.x;
    const int klim = (bm + 1) * 128;
    gemm_pv_core(reinterpret_cast<const bf16*>(g_scores + z * S_ * S_), S_,
                 g_qkv + (size_t)b * S_ * O3_ + 2 * HID_ + h * HD_, O3_,
                 g_attn + (size_t)b * S_ * HID_ + h * HD_, HID_,
                 klim, bm);
}

__global__ __launch_bounds__(256, 2) void k_dense(float* __restrict__ out)
{
    gemm_pipe<0, 0>(g_attnH, g_attnL, HID_, g_wdH, g_wdL, HID_, out, HID_,
                    HID_, blockIdx.y, blockIdx.x,
                    nullptr, nullptr, nullptr, nullptr);
}

// ---------------- split kernels (dst globals referenced INSIDE) ----------------
__global__ __launch_bounds__(256) void split_hs_kernel(const float* __restrict__ s)
{
    size_t e = ((size_t)blockIdx.x * 256 + threadIdx.x) * 4;
    float4 v = *reinterpret_cast<const float4*>(s + e);
    split4planar(v, g_hsH + e, g_hsL + e);
}
__global__ __launch_bounds__(256) void split_wq_kernel(const float* __restrict__ s)
{
    size_t e = ((size_t)blockIdx.x * 256 + threadIdx.x) * 4;
    float4 v = *reinterpret_cast<const float4*>(s + e);
    split4planar(v, g_wqH + e, g_wqL + e);
}
__global__ __launch_bounds__(256) void split_wd_kernel(const float* __restrict__ s)
{
    size_t e = ((size_t)blockIdx.x * 256 + threadIdx.x) * 4;
    float4 v = *reinterpret_cast<const float4*>(s + e);
    split4planar(v, g_wdH + e, g_wdL + e);
}
__global__ __launch_bounds__(256) void split_lora_kernel(const float* __restrict__ s)
{
    size_t e = ((size_t)blockIdx.x * 256 + threadIdx.x) * 4;
    float4 v = *reinterpret_cast<const float4*>(s + e);
    split4planar(v, g_lorH + e, g_lorL + e);
}
__global__ __launch_bounds__(256) void split_attn_kernel()
{
    size_t e = ((size_t)blockIdx.x * 256 + threadIdx.x) * 4;
    float4 v = *reinterpret_cast<const float4*>(g_attn + e);
    split4planar(v, g_attnH + e, g_attnL + e);
}

// ---------------- small kernels ----------------
__global__ __launch_bounds__(256) void lora_mid_kernel(
    const float* __restrict__ hs, const float* __restrict__ lin)
{
    const int row = blockIdx.x;
    const int b = row / S_;
    __shared__ float sh[HID_];
    for (int i = threadIdx.x; i < HID_; i += 256) sh[i] = hs[(size_t)row * HID_ + i];
    __syncthreads();
    const int warp = threadIdx.x >> 5, lane = threadIdx.x & 31;
    for (int r = warp; r < R_; r += 8) {
        const float* lrow = lin + ((size_t)b * R_ + r) * HID_;
        float acc = 0.f;
        for (int i = lane; i < HID_; i += 32) acc = fmaf(sh[i], lrow[i], acc);
#pragma unroll
        for (int o = 16; o > 0; o >>= 1) acc += __shfl_xor_sync(0xffffffffu, acc, o);
        if (lane == 0) {
            bf16 h, l;
            split1(acc, h, l);
            g_midH[(size_t)row * R_ + r] = h;
            g_midL[(size_t)row * R_ + r] = l;
        }
    }
}

__global__ __launch_bounds__(256) void rope_kernel(const int* __restrict__ positions)
{
    const int bs = blockIdx.x;
    const int b = bs / S_, s = bs % S_;
    __shared__ float cs[64], sn[64];
    if (threadIdx.x < 64) {
        float inv = powf(10000.f, -(float)threadIdx.x / 64.f);
        float f = (float)positions[s] * inv;
        cs[threadIdx.x] = cosf(f);
        sn[threadIdx.x] = sinf(f);
    }
    __syncthreads();
    const float* base = g_qkv + (size_t)bs * O3_;
    for (int t = threadIdx.x; t < NH_ * 64; t += 256) {
        int h = t >> 6, i = t & 63;
        float c = cs[i], sv = sn[i];
        size_t o = ((size_t)(b * NH_ + h) * S_ + s) * HD_;
        float x1 = base[h * HD_ + i], x2 = base[h * HD_ + 64 + i];
        bf16 hh, ll;
        split1(x1 * c - x2 * sv, hh, ll);  g_qH[o + i] = hh;      g_qL[o + i] = ll;
        split1(x2 * c + x1 * sv, hh, ll);  g_qH[o + 64 + i] = hh; g_qL[o + 64 + i] = ll;
        float y1 = base[HID_ + h * HD_ + i], y2 = base[HID_ + h * HD_ + 64 + i];
        split1(y1 * c - y2 * sv, hh, ll);  g_kH[o + i] = hh;      g_kL[o + i] = ll;
        split1(y2 * c + y1 * sv, hh, ll);  g_kH[o + 64 + i] = hh; g_kL[o + 64 + i] = ll;
    }
}

// causal softmax; converts row to grouped-split bf16 IN PLACE (for PV's A)
__global__ __launch_bounds__(256) void softmax_kernel()
{
    const size_t row = blockIdx.x;
    const int q = (int)(row & (S_ - 1));
    float* p = g_scores + row * S_;
    const int tid = threadIdx.x;
    __shared__ float red[8];

    float4 v = *reinterpret_cast<const float4*>(p + tid * 4);
    const int e0 = tid * 4;

    float m = -1e30f;
    if (e0 + 0 <= q) m = fmaxf(m, v.x);
    if (e0 + 1 <= q) m = fmaxf(m, v.y);
    if (e0 + 2 <= q) m = fmaxf(m, v.z);
    if (e0 + 3 <= q) m = fmaxf(m, v.w);
#pragma unroll
    for (int o = 16; o > 0; o >>= 1) m = fmaxf(m, __shfl_xor_sync(0xffffffffu, m, o));
    if ((tid & 31) == 0) red[tid >> 5] = m;
    __syncthreads();
    float mm = red[0];
#pragma unroll
    for (int i = 1; i < 8; i++) mm = fmaxf(mm, red[i]);

    float4 e;
    e.x = (e0 + 0 <= q) ? __expf(v.x - mm) : 0.f;
    e.y = (e0 + 1 <= q) ? __expf(v.y - mm) : 0.f;
    e.z = (e0 + 2 <= q) ? __expf(v.z - mm) : 0.f;
    e.w = (e0 + 3 <= q) ? __expf(v.w - mm) : 0.f;
    float sum = e.x + e.y + e.z + e.w;
#pragma unroll
    for (int o = 16; o > 0; o >>= 1) sum += __shfl_xor_sync(0xffffffffu, sum, o);
    __syncthreads();
    if ((tid & 31) == 0) red[tid >> 5] = sum;
    __syncthreads();
    float tot = 0.f;
#pragma unroll
    for (int i = 0; i < 8; i++) tot += red[i];
    float inv = 1.f / tot;
    e.x *= inv; e.y *= inv; e.z *= inv; e.w *= inv;

    *reinterpret_cast<uint4*>(p + tid * 4) = split4pack(e);
}

// ---------------- launch ----------------
extern "C" void kernel_launch(void* const* d_in, const int* in_sizes, int n_in,
                              void* d_out, int out_size)
{
    const int*   positions = (const int*)d_in[0];
    const float* hs        = (const float*)d_in[1];
    const float* w_qkv     = (const float*)d_in[2];
    const float* w_dense   = (const float*)d_in[3];
    const float* lora_in   = (const float*)d_in[4];
    const float* lora_out  = (const float*)d_in[5];
    float* out = (float*)d_out;

    const size_t N_HS = (size_t)Bb_ * S_ * HID_;
    const size_t N_WQ = (size_t)O3_ * HID_;
    const size_t N_WD = (size_t)HID_ * HID_;
    const size_t N_LR = (size_t)Bb_ * O3_ * R_;

    const int SMEM_PIPE = 4 * 4 * 128 * 24 * 2;   // 98304 B
    cudaFuncSetAttribute(k_qkv,    cudaFuncAttributeMaxDynamicSharedMemorySize, SMEM_PIPE);
    cudaFuncSetAttribute(k_scores, cudaFuncAttributeMaxDynamicSharedMemorySize, SMEM_PIPE);
    cudaFuncSetAttribute(k_dense,  cudaFuncAttributeMaxDynamicSharedMemorySize, SMEM_PIPE);

    split_hs_kernel<<<(unsigned)(N_HS / 1024), 256>>>(hs);
    split_wq_kernel<<<(unsigned)(N_WQ / 1024), 256>>>(w_qkv);
    split_lora_kernel<<<(unsigned)(N_LR / 1024), 256>>>(lora_out);

    lora_mid_kernel<<<Bb_ * S_, 256>>>(hs, lora_in);

    k_qkv<<<dim3(O3_ / 128, (Bb_ * S_) / 128), 256, SMEM_PIPE>>>();

    rope_kernel<<<Bb_ * S_, 256>>>(positions);

    k_scores<<<dim3(S_ / 128, S_ / 128, Bb_ * NH_), 256, SMEM_PIPE>>>();

    split_wd_kernel<<<(unsigned)(N_WD / 1024), 256>>>(w_dense);

    softmax_kernel<<<Bb_ * NH_ * S_, 256>>>();

    k_pv<<<dim3(S_ / 128, Bb_ * NH_), 256>>>();

    split_attn_kernel<<<(unsigned)(N_HS / 1024), 256>>>();

    k_dense<<<dim3(HID_ / 128, (Bb_ * S_) / 128), 256, SMEM_PIPE>>>(out);
}

// round 14
// speedup vs baseline: 1.0907x; 1.0907x over previous
#include <cuda_runtime.h>
#include <cuda_bf16.h>
#include <mma.h>
#include <math.h>
#include <stdint.h>
#include <type_traits>

using namespace nvcuda;

#define Bb_ 4
#define S_ 1024
#define HID_ 4096
#define NH_ 32
#define HD_ 128
#define O3_ 12288
#define R_ 32
#define SCALE_ 0.08838834764831845f

typedef __nv_bfloat16 bf16;

// RULES (hard-won): device globals referenced ONLY inside kernel bodies.
// No tcgen05 (harness targets compute_103; 'a'-features rejected by ptxas).

// ---- proven 6-symbol buffer set (914 MB) ----
__device__ float g_qkv[(size_t)Bb_ * S_ * O3_];        // fp32 qkv; q-region reused for planar V
__device__ float g_mid[Bb_ * S_ * R_];                 // grouped bf16 mid (content-level)
__device__ float g_q[(size_t)Bb_ * NH_ * S_ * HD_];    // grouped bf16 q
__device__ float g_k[(size_t)Bb_ * NH_ * S_ * HD_];    // grouped k; later wd presplit
__device__ float g_scores[(size_t)Bb_ * NH_ * S_ * S_];// wq presplit -> scores -> grouped probs
__device__ float g_attn[(size_t)Bb_ * S_ * HID_];      // hs presplit -> fp32 attn

// Grouped-split layout in a region viewed as bf16*:
// logical fp32 element e -> group g=e/4, pos j=e%4: hi at 8g+j, lo at 8g+4+j.

__device__ __forceinline__ void split1(float x, bf16& h, bf16& l) {
    h = __float2bfloat16(x);
    l = __float2bfloat16(x - __bfloat162float(h));
}

__device__ __forceinline__ void split4store(float4 v, bf16* hp, bf16* lp) {
    bf16 h0, h1, h2, h3, l0, l1, l2, l3;
    split1(v.x, h0, l0); split1(v.y, h1, l1);
    split1(v.z, h2, l2); split1(v.w, h3, l3);
    __nv_bfloat162 a, b, c, d;
    a.x = h0; a.y = h1; b.x = h2; b.y = h3;
    c.x = l0; c.y = l1; d.x = l2; d.y = l3;
    *reinterpret_cast<__nv_bfloat162*>(hp)     = a;
    *reinterpret_cast<__nv_bfloat162*>(hp + 2) = b;
    *reinterpret_cast<__nv_bfloat162*>(lp)     = c;
    *reinterpret_cast<__nv_bfloat162*>(lp + 2) = d;
}

__device__ __forceinline__ uint4 split4pack(float4 v) {
    bf16 h0, h1, h2, h3, l0, l1, l2, l3;
    split1(v.x, h0, l0); split1(v.y, h1, l1);
    split1(v.z, h2, l2); split1(v.w, h3, l3);
    __nv_bfloat162 a, b, c, d;
    a.x = h0; a.y = h1; b.x = h2; b.y = h3;
    c.x = l0; c.y = l1; d.x = l2; d.y = l3;
    uint4 r;
    r.x = *reinterpret_cast<uint32_t*>(&a);
    r.y = *reinterpret_cast<uint32_t*>(&b);
    r.z = *reinterpret_cast<uint32_t*>(&c);
    r.w = *reinterpret_cast<uint32_t*>(&d);
    return r;
}

// ---------------- pipelined wmma split GEMM core (R11 skeleton) ----------------
// AMODE: 0 = fp32 rows (in-loop split), 1 = grouped-presplit bf16 rows
// BMODE: 1 = NT grouped-presplit, 3 = K-major planar presplit (Bv=H plane, Bv2=L plane)
// LORA tail: A grouped from midv, B fp32 from lorav (in-loop split).
template <int AMODE, int BMODE, int LORA, int SCALEOUT>
__device__ __forceinline__ void gemm_core(
    const void* __restrict__ Av, const int lda,
    const void* __restrict__ Bv, const void* __restrict__ Bv2, const int ldb,
    float* __restrict__ C, const int ldc,
    const int klim, const int bm, const int bn,
    const void* __restrict__ midv, const float* __restrict__ lorav)
{
    __shared__ __align__(16) bf16 smA[2][2][128][24];            // 24KB
    constexpr int BSTG = (BMODE == 3) ? (16 * 136) : (128 * 24);
    __shared__ __align__(16) bf16 smB[2][2 * BSTG];

    const int t = threadIdx.x;
    const int warp = t >> 5;
    const int wm = warp >> 2, wn = warp & 3;

    wmma::fragment<wmma::accumulator, 16, 16, 16, float> cfr[4][2];
#pragma unroll
    for (int mi = 0; mi < 4; mi++)
#pragma unroll
        for (int ni = 0; ni < 2; ni++) wmma::fill_fragment(cfr[mi][ni], 0.0f);

    const int kT = klim >> 4;
    const int total = kT + (LORA ? (R_ / 16) : 0);

    float4 fA[2], fB[2];
    uint4  uA[2], uB[2];
    uint2  uBh[2], uBl[2];

    auto loadT = [&](int tt) {
        const bool tail = LORA && (tt >= kT);
        const int k0 = tail ? ((tt - kT) << 4) : (tt << 4);
#pragma unroll
        for (int i = 0; i < 2; i++) {
            int idx = i * 256 + t;
            int row = idx >> 2, q4 = (idx & 3) * 4;
            // ---- A ----
            if (AMODE == 1) {
                const bf16* src = tail
                    ? ((const bf16*)midv + (size_t)(bm * 128 + row) * (2 * R_) + 2 * (k0 + q4))
                    : ((const bf16*)Av + (size_t)(bm * 128 + row) * (2 * lda) + 2 * (k0 + q4));
                uA[i] = *reinterpret_cast<const uint4*>(src);
            } else {
                fA[i] = *reinterpret_cast<const float4*>(
                    (const float*)Av + (size_t)(bm * 128 + row) * lda + k0 + q4);
            }
            // ---- B ----
            if (BMODE == 1) {
                if (tail) {
                    fB[i] = *reinterpret_cast<const float4*>(
                        lorav + (size_t)(bn * 128 + row) * R_ + k0 + q4);
                } else {
                    const bf16* src = (const bf16*)Bv
                        + (size_t)(bn * 128 + row) * (2 * ldb) + 2 * (k0 + q4);
                    uB[i] = *reinterpret_cast<const uint4*>(src);
                }
            } else {  // BMODE == 3: K-major planar presplit
                int kr = idx >> 5, nc = (idx & 31) * 4;
                uBh[i] = *reinterpret_cast<const uint2*>(
                    (const bf16*)Bv + (size_t)(k0 + kr) * ldb + nc);
                uBl[i] = *reinterpret_cast<const uint2*>(
                    (const bf16*)Bv2 + (size_t)(k0 + kr) * ldb + nc);
            }
        }
    };

    auto storeT = [&](int st, int tt) {
        const bool tail = LORA && (tt >= kT);
#pragma unroll
        for (int i = 0; i < 2; i++) {
            int idx = i * 256 + t;
            int row = idx >> 2, q4 = (idx & 3) * 4;
            if (AMODE == 1) {
                *reinterpret_cast<uint2*>(&smA[st][0][row][q4]) = make_uint2(uA[i].x, uA[i].y);
                *reinterpret_cast<uint2*>(&smA[st][1][row][q4]) = make_uint2(uA[i].z, uA[i].w);
            } else {
                split4store(fA[i], &smA[st][0][row][q4], &smA[st][1][row][q4]);
            }
            if (BMODE == 1) {
                if (tail) {
                    split4store(fB[i], &smB[st][row * 24 + q4], &smB[st][BSTG + row * 24 + q4]);
                } else {
                    *reinterpret_cast<uint2*>(&smB[st][row * 24 + q4]) = make_uint2(uB[i].x, uB[i].y);
                    *reinterpret_cast<uint2*>(&smB[st][BSTG + row * 24 + q4]) = make_uint2(uB[i].z, uB[i].w);
                }
            } else {
                int kr = idx >> 5, nc = (idx & 31) * 4;
                *reinterpret_cast<uint2*>(&smB[st][kr * 136 + nc]) = uBh[i];
                *reinterpret_cast<uint2*>(&smB[st][BSTG + kr * 136 + nc]) = uBl[i];
            }
        }
    };

    loadT(0);
    storeT(0, 0);
    __syncthreads();

    using BLay = typename std::conditional<BMODE == 3, wmma::row_major, wmma::col_major>::type;

    for (int tt = 0; tt < total; tt++) {
        if (tt + 1 < total) loadT(tt + 1);
        const int st = tt & 1;

        wmma::fragment<wmma::matrix_b, 16, 16, 16, bf16, BLay> bH[2], bL[2];
#pragma unroll
        for (int ni = 0; ni < 2; ni++) {
            if (BMODE == 3) {
                wmma::load_matrix_sync(bH[ni], &smB[st][wn * 32 + ni * 16], 136);
                wmma::load_matrix_sync(bL[ni], &smB[st][BSTG + wn * 32 + ni * 16], 136);
            } else {
                wmma::load_matrix_sync(bH[ni], &smB[st][(wn * 32 + ni * 16) * 24], 24);
                wmma::load_matrix_sync(bL[ni], &smB[st][BSTG + (wn * 32 + ni * 16) * 24], 24);
            }
        }
#pragma unroll
        for (int mi = 0; mi < 4; mi++) {
            wmma::fragment<wmma::matrix_a, 16, 16, 16, bf16, wmma::row_major> aH, aL;
            wmma::load_matrix_sync(aH, &smA[st][0][wm * 64 + mi * 16][0], 24);
            wmma::load_matrix_sync(aL, &smA[st][1][wm * 64 + mi * 16][0], 24);
#pragma unroll
            for (int ni = 0; ni < 2; ni++) {
                wmma::mma_sync(cfr[mi][ni], aH, bH[ni], cfr[mi][ni]);
                wmma::mma_sync(cfr[mi][ni], aH, bL[ni], cfr[mi][ni]);
                wmma::mma_sync(cfr[mi][ni], aL, bH[ni], cfr[mi][ni]);
            }
        }
        if (tt + 1 < total) storeT((tt + 1) & 1, tt + 1);
        __syncthreads();
    }

#pragma unroll
    for (int mi = 0; mi < 4; mi++)
#pragma unroll
        for (int ni = 0; ni < 2; ni++) {
            if (SCALEOUT) {
#pragma unroll
                for (int e = 0; e < cfr[mi][ni].num_elements; e++) cfr[mi][ni].x[e] *= SCALE_;
            }
            wmma::store_matrix_sync(
                C + (size_t)(bm * 128 + wm * 64 + mi * 16) * ldc + bn * 128 + wn * 32 + ni * 16,
                cfr[mi][ni], ldc, wmma::mem_row_major);
        }
}

// ---------------- GEMM wrapper kernels ----------------
__global__ __launch_bounds__(256, 2) void k_qkv(const float* __restrict__ lora_out)
{
    const int b = (int)(blockIdx.y >> 3);
    gemm_core<1, 1, 1, 0>(g_attn, HID_, g_scores, nullptr, HID_, g_qkv, O3_, HID_,
                          blockIdx.y, blockIdx.x,
                          g_mid, lora_out + (size_t)b * O3_ * R_);
}

__global__ __launch_bounds__(256, 2) void k_scores()
{
    const int ti = (int)blockIdx.x;                // lower-triangle tile index [0,36)
    int bm = (int)((sqrtf(8.f * ti + 1.f) - 1.f) * 0.5f);
    while ((bm + 1) * (bm + 2) / 2 <= ti) ++bm;
    while (bm * (bm + 1) / 2 > ti) --bm;
    const int bn = ti - bm * (bm + 1) / 2;
    const size_t z = blockIdx.y;
    gemm_core<1, 1, 0, 1>(g_q + z * S_ * HD_, HD_, g_k + z * S_ * HD_, nullptr, HD_,
                          g_scores + z * S_ * S_, S_, HD_,
                          bm, bn, nullptr, nullptr);
}

__global__ __launch_bounds__(256, 2) void k_pv()
{
    const size_t z = blockIdx.y;
    const int b = (int)(z >> 5), h = (int)(z & 31);
    const int bm = (int)blockIdx.x;
    const int klim = (bm + 1) * 128;
    // planar V lives in the dead q-region of g_qkv rows: vH at [0,HID_) bf16, vL at [HID_,2*HID_)
    const bf16* vbase = reinterpret_cast<const bf16*>(g_qkv + (size_t)b * S_ * O3_);
    gemm_core<1, 3, 0, 0>(g_scores + z * S_ * S_, S_,
                          vbase + h * HD_, vbase + HID_ + h * HD_, 2 * O3_,
                          g_attn + (size_t)b * S_ * HID_ + h * HD_, HID_,
                          klim, bm, 0, nullptr, nullptr);
}

__global__ __launch_bounds__(256, 2) void k_dense(float* __restrict__ out)
{
    gemm_core<0, 1, 0, 0>(g_attn, HID_, g_k, nullptr, HID_, out, HID_, HID_,
                          blockIdx.y, blockIdx.x, nullptr, nullptr);
}

// ---------------- split kernels (dst globals INSIDE) ----------------
__global__ __launch_bounds__(256) void split_hs_kernel(const float* __restrict__ s)
{
    size_t e = ((size_t)blockIdx.x * 256 + threadIdx.x) * 4;
    float4 v = *reinterpret_cast<const float4*>(s + e);
    *reinterpret_cast<uint4*>(reinterpret_cast<bf16*>(g_attn) + 2 * e) = split4pack(v);
}
__global__ __launch_bounds__(256) void split_wq_kernel(const float* __restrict__ s)
{
    size_t e = ((size_t)blockIdx.x * 256 + threadIdx.x) * 4;
    float4 v = *reinterpret_cast<const float4*>(s + e);
    *reinterpret_cast<uint4*>(reinterpret_cast<bf16*>(g_scores) + 2 * e) = split4pack(v);
}
__global__ __launch_bounds__(256) void split_wd_kernel(const float* __restrict__ s)
{
    size_t e = ((size_t)blockIdx.x * 256 + threadIdx.x) * 4;
    float4 v = *reinterpret_cast<const float4*>(s + e);
    *reinterpret_cast<uint4*>(reinterpret_cast<bf16*>(g_k) + 2 * e) = split4pack(v);
}

// ---------------- small kernels ----------------
__global__ __launch_bounds__(256) void lora_mid_kernel(
    const float* __restrict__ hs, const float* __restrict__ lin)
{
    const int row = blockIdx.x;
    const int b = row / S_;
    __shared__ float sh[HID_];
    for (int i = threadIdx.x; i < HID_; i += 256) sh[i] = hs[(size_t)row * HID_ + i];
    __syncthreads();
    const int warp = threadIdx.x >> 5, lane = threadIdx.x & 31;
    for (int r = warp; r < R_; r += 8) {
        const float* lrow = lin + ((size_t)b * R_ + r) * HID_;
        float acc = 0.f;
        for (int i = lane * 4; i < HID_; i += 128) {
            float4 a = *reinterpret_cast<const float4*>(&sh[i]);
            float4 w = *reinterpret_cast<const float4*>(&lrow[i]);
            acc = fmaf(a.x, w.x, acc); acc = fmaf(a.y, w.y, acc);
            acc = fmaf(a.z, w.z, acc); acc = fmaf(a.w, w.w, acc);
        }
#pragma unroll
        for (int o = 16; o > 0; o >>= 1) acc += __shfl_xor_sync(0xffffffffu, acc, o);
        if (lane == 0) {
            bf16* mp = reinterpret_cast<bf16*>(g_mid);
            size_t base = (size_t)row * (2 * R_) + 8 * (r >> 2) + (r & 3);
            bf16 h, l;
            split1(acc, h, l);
            mp[base] = h;
            mp[base + 4] = l;
        }
    }
}

__global__ __launch_bounds__(256) void rope_kernel(const int* __restrict__ positions)
{
    const int bs = blockIdx.x;
    const int b = bs / S_, s = bs % S_;
    __shared__ float cs[64], sn[64];
    if (threadIdx.x < 64) {
        float inv = powf(10000.f, -(float)threadIdx.x / 64.f);
        float f = (float)positions[s] * inv;
        cs[threadIdx.x] = cosf(f);
        sn[threadIdx.x] = sinf(f);
    }
    __syncthreads();
    float* base = g_qkv + (size_t)bs * O3_;
    bf16* qp = reinterpret_cast<bf16*>(g_q);
    bf16* kp = reinterpret_cast<bf16*>(g_k);
    for (int t = threadIdx.x; t < NH_ * 64; t += 256) {
        int h = t >> 6, i = t & 63;
        float c = cs[i], sv = sn[i];
        size_t row = (size_t)(b * NH_ + h) * S_ + s;
        size_t o1 = row * 256 + 8 * (i >> 2) + (i & 3);
        size_t o2 = row * 256 + 8 * ((64 + i) >> 2) + (i & 3);
        float x1 = base[h * HD_ + i], x2 = base[h * HD_ + 64 + i];
        bf16 h0, l0;
        split1(x1 * c - x2 * sv, h0, l0);  qp[o1] = h0; qp[o1 + 4] = l0;
        split1(x2 * c + x1 * sv, h0, l0);  qp[o2] = h0; qp[o2 + 4] = l0;
        float y1 = base[HID_ + h * HD_ + i], y2 = base[HID_ + h * HD_ + 64 + i];
        split1(y1 * c - y2 * sv, h0, l0);  kp[o1] = h0; kp[o1 + 4] = l0;
        split1(y2 * c + y1 * sv, h0, l0);  kp[o2] = h0; kp[o2 + 4] = l0;
    }
    __syncthreads();   // all q-region reads complete before overwrite below
    // planar V split into dead q-region of this row: vH at bf16 [0,HID_), vL at [HID_,2*HID_)
    bf16* vp = reinterpret_cast<bf16*>(base);
    for (int t = threadIdx.x; t < HID_; t += 256) {
        bf16 h0, l0;
        split1(base[2 * HID_ + t], h0, l0);
        vp[t] = h0;
        vp[HID_ + t] = l0;
    }
}

// causal softmax; converts row to grouped-split bf16 IN PLACE (PV's A)
__global__ __launch_bounds__(256) void softmax_kernel()
{
    const size_t row = blockIdx.x;
    const int q = (int)(row & (S_ - 1));
    float* p = g_scores + row * S_;
    const int tid = threadIdx.x;
    __shared__ float red[8];

    float4 v = *reinterpret_cast<const float4*>(p + tid * 4);
    const int e0 = tid * 4;

    float m = -1e30f;
    if (e0 + 0 <= q) m = fmaxf(m, v.x);
    if (e0 + 1 <= q) m = fmaxf(m, v.y);
    if (e0 + 2 <= q) m = fmaxf(m, v.z);
    if (e0 + 3 <= q) m = fmaxf(m, v.w);
#pragma unroll
    for (int o = 16; o > 0; o >>= 1) m = fmaxf(m, __shfl_xor_sync(0xffffffffu, m, o));
    if ((tid & 31) == 0) red[tid >> 5] = m;
    __syncthreads();
    float mm = red[0];
#pragma unroll
    for (int i = 1; i < 8; i++) mm = fmaxf(mm, red[i]);

    float4 e;
    e.x = (e0 + 0 <= q) ? __expf(v.x - mm) : 0.f;
    e.y = (e0 + 1 <= q) ? __expf(v.y - mm) : 0.f;
    e.z = (e0 + 2 <= q) ? __expf(v.z - mm) : 0.f;
    e.w = (e0 + 3 <= q) ? __expf(v.w - mm) : 0.f;
    float sum = e.x + e.y + e.z + e.w;
#pragma unroll
    for (int o = 16; o > 0; o >>= 1) sum += __shfl_xor_sync(0xffffffffu, sum, o);
    __syncthreads();
    if ((tid & 31) == 0) red[tid >> 5] = sum;
    __syncthreads();
    float tot = 0.f;
#pragma unroll
    for (int i = 0; i < 8; i++) tot += red[i];
    float inv = 1.f / tot;
    e.x *= inv; e.y *= inv; e.z *= inv; e.w *= inv;

    *reinterpret_cast<uint4*>(p + tid * 4) = split4pack(e);
}

// ---------------- launch ----------------
extern "C" void kernel_launch(void* const* d_in, const int* in_sizes, int n_in,
                              void* d_out, int out_size)
{
    const int*   positions = (const int*)d_in[0];
    const float* hs        = (const float*)d_in[1];
    const float* w_qkv     = (const float*)d_in[2];
    const float* w_dense   = (const float*)d_in[3];
    const float* lora_in   = (const float*)d_in[4];
    const float* lora_out  = (const float*)d_in[5];
    float* out = (float*)d_out;

    const size_t N_HS = (size_t)Bb_ * S_ * HID_;
    const size_t N_WQ = (size_t)O3_ * HID_;
    const size_t N_WD = (size_t)HID_ * HID_;

    split_hs_kernel<<<(unsigned)(N_HS / 1024), 256>>>(hs);
    split_wq_kernel<<<(unsigned)(N_WQ / 1024), 256>>>(w_qkv);

    lora_mid_kernel<<<Bb_ * S_, 256>>>(hs, lora_in);

    k_qkv<<<dim3(O3_ / 128, (Bb_ * S_) / 128), 256>>>(lora_out);

    rope_kernel<<<Bb_ * S_, 256>>>(positions);

    k_scores<<<dim3(36, Bb_ * NH_), 256>>>();

    // g_k dead after k_scores: stash wd presplit there for k_dense
    split_wd_kernel<<<(unsigned)(N_WD / 1024), 256>>>(w_dense);

    softmax_kernel<<<Bb_ * NH_ * S_, 256>>>();

    k_pv<<<dim3(S_ / 128, Bb_ * NH_), 256>>>();

    k_dense<<<dim3(HID_ / 128, (Bb_ * S_) / 128), 256>>>(out);
}